// round 1
// baseline (speedup 1.0000x reference)
#include <cuda_runtime.h>
#include <cuda_bf16.h>
#include <math.h>

#define SEQLEN  4096
#define DMODEL  2048
#define DINNER  4096
#define DSTATE  128
#define NHEADS  64
#define HEADDIM 64
#define CONVDIM 4352
#define DPROJ   8512

// ---------------- scratch (device globals; no allocation allowed) ------------
__device__ float g_zxbcdt[(size_t)SEQLEN * DPROJ];   // in_proj output
__device__ float g_xBC[(size_t)SEQLEN * CONVDIM];    // conv+silu output
__device__ float g_dt[(size_t)SEQLEN * NHEADS];      // softplus(dt)
__device__ float g_dA[(size_t)SEQLEN * NHEADS];      // exp(dt * A)
__device__ float g_y[(size_t)SEQLEN * DINNER];       // scan output (+D skip)
__device__ float g_yn[(size_t)SEQLEN * DINNER];      // gated+normed

// ---------------- SGEMM: C[M,N] = A[M,K] * B[N,K]^T --------------------------
// A row-major MxK, B row-major NxK (weight layout), C row-major MxN.
// Requires M % 128 == 0, K % 16 == 0. N handled with guards.
__global__ __launch_bounds__(256, 2)
void sgemm_tn(const float* __restrict__ A, const float* __restrict__ B,
              float* __restrict__ C, int M, int N, int K)
{
    __shared__ float As[16][132];
    __shared__ float Bs[16][132];

    const int bm  = blockIdx.y * 128;
    const int bn  = blockIdx.x * 128;
    const int tid = threadIdx.x;
    const int tx  = tid & 15;
    const int ty  = tid >> 4;
    const int lr  = tid >> 2;          // 0..63
    const int lk  = (tid & 3) << 2;    // 0,4,8,12

    float acc[8][8];
#pragma unroll
    for (int i = 0; i < 8; i++)
#pragma unroll
        for (int j = 0; j < 8; j++) acc[i][j] = 0.f;

    for (int k0 = 0; k0 < K; k0 += 16) {
#pragma unroll
        for (int half = 0; half < 2; half++) {
            const int r = lr + half * 64;
            float4 va = *reinterpret_cast<const float4*>(
                &A[(size_t)(bm + r) * K + k0 + lk]);
            As[lk + 0][r] = va.x; As[lk + 1][r] = va.y;
            As[lk + 2][r] = va.z; As[lk + 3][r] = va.w;

            const int n = bn + r;
            float4 vb = make_float4(0.f, 0.f, 0.f, 0.f);
            if (n < N)
                vb = *reinterpret_cast<const float4*>(
                    &B[(size_t)n * K + k0 + lk]);
            Bs[lk + 0][r] = vb.x; Bs[lk + 1][r] = vb.y;
            Bs[lk + 2][r] = vb.z; Bs[lk + 3][r] = vb.w;
        }
        __syncthreads();
#pragma unroll
        for (int kk = 0; kk < 16; kk++) {
            float a[8], b[8];
            *(float4*)&a[0] = *(const float4*)&As[kk][ty * 8];
            *(float4*)&a[4] = *(const float4*)&As[kk][ty * 8 + 4];
            *(float4*)&b[0] = *(const float4*)&Bs[kk][tx * 8];
            *(float4*)&b[4] = *(const float4*)&Bs[kk][tx * 8 + 4];
#pragma unroll
            for (int i = 0; i < 8; i++)
#pragma unroll
                for (int j = 0; j < 8; j++)
                    acc[i][j] = fmaf(a[i], b[j], acc[i][j]);
        }
        __syncthreads();
    }

#pragma unroll
    for (int i = 0; i < 8; i++) {
        const int m = bm + ty * 8 + i;
#pragma unroll
        for (int j = 0; j < 8; j++) {
            const int n = bn + tx * 8 + j;
            if (n < N) C[(size_t)m * N + n] = acc[i][j];
        }
    }
}

// ---------------- depthwise causal conv(4) + SiLU ----------------------------
__global__ void conv_silu_kernel(const float* __restrict__ zx,
                                 const float* __restrict__ cw,
                                 const float* __restrict__ cb,
                                 float* __restrict__ xBC)
{
    const int idx = blockIdx.x * blockDim.x + threadIdx.x;
    if (idx >= SEQLEN * CONVDIM) return;
    const int l = idx / CONVDIM;
    const int c = idx - l * CONVDIM;
    float a = cb[c];
    const float* col = zx + DINNER + c;   // xBC_pre column c, row stride DPROJ
#pragma unroll
    for (int t = 0; t < 4; t++) {
        const int ll = l - 3 + t;
        if (ll >= 0) a = fmaf(col[(size_t)ll * DPROJ], cw[c * 4 + t], a);
    }
    const float sg = 1.f / (1.f + expf(-a));
    xBC[idx] = a * sg;
}

// ---------------- dt = softplus(raw + bias), dA = exp(dt * A) ----------------
__global__ void dt_kernel(const float* __restrict__ zx,
                          const float* __restrict__ dt_bias,
                          const float* __restrict__ A_log,
                          float* __restrict__ dt, float* __restrict__ dA)
{
    const int idx = blockIdx.x * blockDim.x + threadIdx.x;
    if (idx >= SEQLEN * NHEADS) return;
    const int l = idx >> 6;
    const int h = idx & 63;
    const float v = zx[(size_t)l * DPROJ + DINNER + CONVDIM + h] + dt_bias[h];
    const float d = (v > 20.f) ? v : log1pf(expf(v));
    dt[idx] = d;
    dA[idx] = expf(-d * expf(A_log[h]));
}

// ---------------- sequential selective scan ----------------------------------
// grid = NHEADS*4 blocks (head h = blockIdx>>2, 16-wide headdim slice pblk),
// block = 128 threads: pl = tid>>3 picks p within slice, ng = tid&7 picks 16
// state columns n = ng + 8*j (stride-8 => conflict-free LDS, shfl-reducible).
__global__ __launch_bounds__(128)
void scan_kernel(const float* __restrict__ xBC, const float* __restrict__ dtv,
                 const float* __restrict__ dAv, const float* __restrict__ Dvec,
                 float* __restrict__ y)
{
    const int h    = blockIdx.x >> 2;
    const int pblk = blockIdx.x & 3;
    const int tid  = threadIdx.x;
    const int pl   = tid >> 3;     // 0..15
    const int ng   = tid & 7;      // 0..7
    const int p    = pblk * 16 + pl;
    const float Dh = Dvec[h];

    __shared__ float sB[8][128];
    __shared__ float sC[8][128];
    __shared__ float sx[8][16];
    __shared__ float sdt[8];
    __shared__ float sda[8];

    float s[16];
#pragma unroll
    for (int j = 0; j < 16; j++) s[j] = 0.f;

    for (int l0 = 0; l0 < SEQLEN; l0 += 8) {
        __syncthreads();
#pragma unroll
        for (int k = 0; k < 8; k++) {
            const float* row = xBC + (size_t)(l0 + k) * CONVDIM;
            sB[k][tid] = row[DINNER + tid];
            sC[k][tid] = row[DINNER + DSTATE + tid];
        }
        {
            const int tt = tid >> 4, pp = tid & 15;  // 128 threads cover 8x16
            sx[tt][pp] = xBC[(size_t)(l0 + tt) * CONVDIM + h * HEADDIM + pblk * 16 + pp];
        }
        if (tid < 8)       sdt[tid]     = dtv[(l0 + tid) * NHEADS + h];
        else if (tid < 16) sda[tid - 8] = dAv[(l0 + tid - 8) * NHEADS + h];
        __syncthreads();

#pragma unroll
        for (int t = 0; t < 8; t++) {
            const float dtl = sdt[t];
            const float e   = sda[t];
            const float xv  = sx[t][pl];
            const float xp  = xv * dtl;
            float accv = 0.f;
#pragma unroll
            for (int j = 0; j < 16; j++) {
                const int n = ng + (j << 3);
                const float sv = fmaf(s[j], e, xp * sB[t][n]);
                s[j] = sv;
                accv = fmaf(sC[t][n], sv, accv);
            }
            accv += __shfl_xor_sync(0xffffffffu, accv, 1);
            accv += __shfl_xor_sync(0xffffffffu, accv, 2);
            accv += __shfl_xor_sync(0xffffffffu, accv, 4);
            if (ng == 0)
                y[(size_t)(l0 + t) * DINNER + h * HEADDIM + p] = accv + xv * Dh;
        }
    }
}

// ---------------- gate (y * silu(z)) + RMSNorm -------------------------------
__global__ __launch_bounds__(256)
void gate_norm_kernel(const float* __restrict__ y, const float* __restrict__ zx,
                      const float* __restrict__ nw, float* __restrict__ yn)
{
    __shared__ float buf[DINNER];
    __shared__ float red[8];
    const int l = blockIdx.x, tid = threadIdx.x;
    const float* yrow = y + (size_t)l * DINNER;
    const float* zrow = zx + (size_t)l * DPROJ;   // z = cols [0, DINNER)

    float part = 0.f;
    for (int i = tid; i < DINNER; i += 256) {
        const float z = zrow[i];
        const float g = z / (1.f + expf(-z));
        const float v = yrow[i] * g;
        buf[i] = v;
        part = fmaf(v, v, part);
    }
#pragma unroll
    for (int o = 16; o; o >>= 1) part += __shfl_xor_sync(0xffffffffu, part, o);
    if ((tid & 31) == 0) red[tid >> 5] = part;
    __syncthreads();
    if (tid < 8) {
        float v = red[tid];
#pragma unroll
        for (int o = 4; o; o >>= 1) v += __shfl_xor_sync(0xffu, v, o);
        if (tid == 0) red[0] = v;
    }
    __syncthreads();
    const float r = rsqrtf(red[0] / (float)DINNER + 1e-5f);
    for (int i = tid; i < DINNER; i += 256)
        yn[(size_t)l * DINNER + i] = buf[i] * r * nw[i];
}

// ---------------- launcher ---------------------------------------------------
extern "C" void kernel_launch(void* const* d_in, const int* in_sizes, int n_in,
                              void* d_out, int out_size)
{
    const float* u          = (const float*)d_in[0];
    const float* in_proj_w  = (const float*)d_in[1];
    const float* conv_w     = (const float*)d_in[2];
    const float* conv_b     = (const float*)d_in[3];
    const float* dt_bias    = (const float*)d_in[4];
    const float* A_log      = (const float*)d_in[5];
    const float* Dvec       = (const float*)d_in[6];
    const float* norm_w     = (const float*)d_in[7];
    const float* out_proj_w = (const float*)d_in[8];
    float* out = (float*)d_out;

    float *zx, *xBC, *dt, *dA, *y, *yn;
    cudaGetSymbolAddress((void**)&zx,  g_zxbcdt);
    cudaGetSymbolAddress((void**)&xBC, g_xBC);
    cudaGetSymbolAddress((void**)&dt,  g_dt);
    cudaGetSymbolAddress((void**)&dA,  g_dA);
    cudaGetSymbolAddress((void**)&y,   g_y);
    cudaGetSymbolAddress((void**)&yn,  g_yn);

    // 1) zxbcdt = u @ in_proj_w^T   (4096 x 8512, K=2048)
    sgemm_tn<<<dim3((DPROJ + 127) / 128, SEQLEN / 128), 256>>>(
        u, in_proj_w, zx, SEQLEN, DPROJ, DMODEL);

    // 2) causal depthwise conv + SiLU
    conv_silu_kernel<<<(SEQLEN * CONVDIM + 255) / 256, 256>>>(
        zx, conv_w, conv_b, xBC);

    // 3) dt / decay precompute
    dt_kernel<<<(SEQLEN * NHEADS + 255) / 256, 256>>>(
        zx, dt_bias, A_log, dt, dA);

    // 4) selective scan (+ D skip)
    scan_kernel<<<NHEADS * 4, 128>>>(xBC, dt, dA, Dvec, y);

    // 5) gate + RMSNorm
    gate_norm_kernel<<<SEQLEN, 256>>>(y, zx, norm_w, yn);

    // 6) out = yn @ out_proj_w^T   (4096 x 2048, K=4096)
    sgemm_tn<<<dim3(DMODEL / 128, SEQLEN / 128), 256>>>(
        yn, out_proj_w, out, SEQLEN, DMODEL, DINNER);
}

// round 3
// speedup vs baseline: 1.5777x; 1.5777x over previous
#include <cuda_runtime.h>
#include <cuda_bf16.h>
#include <math.h>

#define SEQLEN  4096
#define DMODEL  2048
#define DINNER  4096
#define DSTATE  128
#define NHEADS  64
#define HEADDIM 64
#define CONVDIM 4352
#define DPROJ   8512

// ---------------- scratch (device globals; no allocation allowed) ------------
__device__ float g_zxbcdt[(size_t)SEQLEN * DPROJ];   // in_proj output
__device__ float g_xBC[(size_t)SEQLEN * CONVDIM];    // conv+silu output
__device__ float g_dt[(size_t)SEQLEN * NHEADS];      // softplus(dt)
__device__ float g_dA[(size_t)SEQLEN * NHEADS];      // exp(dt * A)
__device__ float g_y[(size_t)SEQLEN * DINNER];       // scan output (+D skip)
__device__ float g_yn[(size_t)SEQLEN * DINNER];      // gated+normed

// ---------------- TF32 tensor-core GEMM: C[M,N] = A[M,K] * B[N,K]^T ----------
// A row-major MxK, B row-major NxK, C row-major MxN.
// Requires M % 128 == 0, K % 16 == 0. N guarded.
// Block 256 thr = 8 warps; tile 128x128x16; warp tile 64x32 via m16n8k8 tf32.
__device__ __forceinline__ unsigned f2tf32(float v) {
    unsigned r;
    asm volatile("cvt.rna.tf32.f32 %0, %1;" : "=r"(r) : "f"(v));
    return r;
}

__global__ __launch_bounds__(256, 2)
void mma_gemm_tn(const float* __restrict__ A, const float* __restrict__ B,
                 float* __restrict__ C, int M, int N, int K)
{
    __shared__ float As[16][132];
    __shared__ float Bs[16][132];

    const int bm  = blockIdx.y * 128;
    const int bn  = blockIdx.x * 128;
    const int tid = threadIdx.x;
    const int lr  = tid >> 2;          // 0..63
    const int lk  = (tid & 3) << 2;    // 0,4,8,12

    const int wid  = tid >> 5;         // 0..7
    const int lane = tid & 31;
    const int g    = lane >> 2;        // 0..7
    const int c    = lane & 3;         // 0..3
    const int mb   = (wid & 1) * 64;   // warp m-offset in tile
    const int nb   = (wid >> 1) * 32;  // warp n-offset in tile

    float acc[4][4][4];
#pragma unroll
    for (int i = 0; i < 4; i++)
#pragma unroll
        for (int j = 0; j < 4; j++)
#pragma unroll
            for (int r = 0; r < 4; r++) acc[i][j][r] = 0.f;

    for (int k0 = 0; k0 < K; k0 += 16) {
#pragma unroll
        for (int half = 0; half < 2; half++) {
            const int r = lr + half * 64;
            float4 va = *reinterpret_cast<const float4*>(
                &A[(size_t)(bm + r) * K + k0 + lk]);
            As[lk + 0][r] = __uint_as_float(f2tf32(va.x));
            As[lk + 1][r] = __uint_as_float(f2tf32(va.y));
            As[lk + 2][r] = __uint_as_float(f2tf32(va.z));
            As[lk + 3][r] = __uint_as_float(f2tf32(va.w));

            const int n = bn + r;
            float4 vb = make_float4(0.f, 0.f, 0.f, 0.f);
            if (n < N)
                vb = *reinterpret_cast<const float4*>(
                    &B[(size_t)n * K + k0 + lk]);
            Bs[lk + 0][r] = __uint_as_float(f2tf32(vb.x));
            Bs[lk + 1][r] = __uint_as_float(f2tf32(vb.y));
            Bs[lk + 2][r] = __uint_as_float(f2tf32(vb.z));
            Bs[lk + 3][r] = __uint_as_float(f2tf32(vb.w));
        }
        __syncthreads();

#pragma unroll
        for (int ks = 0; ks < 2; ks++) {
            const int kr0 = ks * 8 + c;
            const int kr4 = kr0 + 4;
            unsigned a[4][4], b[4][2];
#pragma unroll
            for (int mi = 0; mi < 4; mi++) {
                const int m0 = mb + mi * 16;
                a[mi][0] = __float_as_uint(As[kr0][m0 + g]);
                a[mi][1] = __float_as_uint(As[kr0][m0 + g + 8]);
                a[mi][2] = __float_as_uint(As[kr4][m0 + g]);
                a[mi][3] = __float_as_uint(As[kr4][m0 + g + 8]);
            }
#pragma unroll
            for (int ni = 0; ni < 4; ni++) {
                const int n0 = nb + ni * 8;
                b[ni][0] = __float_as_uint(Bs[kr0][n0 + g]);
                b[ni][1] = __float_as_uint(Bs[kr4][n0 + g]);
            }
#pragma unroll
            for (int mi = 0; mi < 4; mi++)
#pragma unroll
                for (int ni = 0; ni < 4; ni++) {
                    asm volatile(
                        "mma.sync.aligned.m16n8k8.row.col.f32.tf32.tf32.f32 "
                        "{%0,%1,%2,%3}, {%4,%5,%6,%7}, {%8,%9}, {%0,%1,%2,%3};"
                        : "+f"(acc[mi][ni][0]), "+f"(acc[mi][ni][1]),
                          "+f"(acc[mi][ni][2]), "+f"(acc[mi][ni][3])
                        : "r"(a[mi][0]), "r"(a[mi][1]), "r"(a[mi][2]), "r"(a[mi][3]),
                          "r"(b[ni][0]), "r"(b[ni][1]));
                }
        }
        __syncthreads();
    }

    // epilogue: d0,d1 -> (row g, cols 2c,2c+1); d2,d3 -> (row g+8)
#pragma unroll
    for (int mi = 0; mi < 4; mi++) {
#pragma unroll
        for (int ni = 0; ni < 4; ni++) {
            const int row0 = bm + mb + mi * 16 + g;
            const int col  = bn + nb + ni * 8 + c * 2;
            if (col < N) {
                *reinterpret_cast<float2*>(&C[(size_t)row0 * N + col]) =
                    make_float2(acc[mi][ni][0], acc[mi][ni][1]);
                *reinterpret_cast<float2*>(&C[(size_t)(row0 + 8) * N + col]) =
                    make_float2(acc[mi][ni][2], acc[mi][ni][3]);
            }
        }
    }
}

// ---------------- depthwise causal conv(4) + SiLU ----------------------------
__global__ void conv_silu_kernel(const float* __restrict__ zx,
                                 const float* __restrict__ cw,
                                 const float* __restrict__ cb,
                                 float* __restrict__ xBC)
{
    const int idx = blockIdx.x * blockDim.x + threadIdx.x;
    if (idx >= SEQLEN * CONVDIM) return;
    const int l = idx / CONVDIM;
    const int c = idx - l * CONVDIM;
    float a = cb[c];
    const float* col = zx + DINNER + c;   // xBC_pre column c, row stride DPROJ
#pragma unroll
    for (int t = 0; t < 4; t++) {
        const int ll = l - 3 + t;
        if (ll >= 0) a = fmaf(col[(size_t)ll * DPROJ], cw[c * 4 + t], a);
    }
    const float sg = 1.f / (1.f + expf(-a));
    xBC[idx] = a * sg;
}

// ---------------- dt = softplus(raw + bias), dA = exp(dt * A) ----------------
__global__ void dt_kernel(const float* __restrict__ zx,
                          const float* __restrict__ dt_bias,
                          const float* __restrict__ A_log,
                          float* __restrict__ dt, float* __restrict__ dA)
{
    const int idx = blockIdx.x * blockDim.x + threadIdx.x;
    if (idx >= SEQLEN * NHEADS) return;
    const int l = idx >> 6;
    const int h = idx & 63;
    const float v = zx[(size_t)l * DPROJ + DINNER + CONVDIM + h] + dt_bias[h];
    const float d = (v > 20.f) ? v : log1pf(expf(v));
    dt[idx] = d;
    dA[idx] = expf(-d * expf(A_log[h]));
}

// ---------------- sequential selective scan ----------------------------------
__global__ __launch_bounds__(128)
void scan_kernel(const float* __restrict__ xBC, const float* __restrict__ dtv,
                 const float* __restrict__ dAv, const float* __restrict__ Dvec,
                 float* __restrict__ y)
{
    const int h    = blockIdx.x >> 2;
    const int pblk = blockIdx.x & 3;
    const int tid  = threadIdx.x;
    const int pl   = tid >> 3;     // 0..15
    const int ng   = tid & 7;      // 0..7
    const int p    = pblk * 16 + pl;
    const float Dh = Dvec[h];

    __shared__ float sB[8][128];
    __shared__ float sC[8][128];
    __shared__ float sx[8][16];
    __shared__ float sdt[8];
    __shared__ float sda[8];

    float s[16];
#pragma unroll
    for (int j = 0; j < 16; j++) s[j] = 0.f;

    for (int l0 = 0; l0 < SEQLEN; l0 += 8) {
        __syncthreads();
#pragma unroll
        for (int k = 0; k < 8; k++) {
            const float* row = xBC + (size_t)(l0 + k) * CONVDIM;
            sB[k][tid] = row[DINNER + tid];
            sC[k][tid] = row[DINNER + DSTATE + tid];
        }
        {
            const int tt = tid >> 4, pp = tid & 15;  // 128 threads cover 8x16
            sx[tt][pp] = xBC[(size_t)(l0 + tt) * CONVDIM + h * HEADDIM + pblk * 16 + pp];
        }
        if (tid < 8)       sdt[tid]     = dtv[(l0 + tid) * NHEADS + h];
        else if (tid < 16) sda[tid - 8] = dAv[(l0 + tid - 8) * NHEADS + h];
        __syncthreads();

#pragma unroll
        for (int t = 0; t < 8; t++) {
            const float dtl = sdt[t];
            const float e   = sda[t];
            const float xv  = sx[t][pl];
            const float xp  = xv * dtl;
            float accv = 0.f;
#pragma unroll
            for (int j = 0; j < 16; j++) {
                const int n = ng + (j << 3);
                const float sv = fmaf(s[j], e, xp * sB[t][n]);
                s[j] = sv;
                accv = fmaf(sC[t][n], sv, accv);
            }
            accv += __shfl_xor_sync(0xffffffffu, accv, 1);
            accv += __shfl_xor_sync(0xffffffffu, accv, 2);
            accv += __shfl_xor_sync(0xffffffffu, accv, 4);
            if (ng == 0)
                y[(size_t)(l0 + t) * DINNER + h * HEADDIM + p] = accv + xv * Dh;
        }
    }
}

// ---------------- gate (y * silu(z)) + RMSNorm -------------------------------
__global__ __launch_bounds__(256)
void gate_norm_kernel(const float* __restrict__ y, const float* __restrict__ zx,
                      const float* __restrict__ nw, float* __restrict__ yn)
{
    __shared__ float buf[DINNER];
    __shared__ float red[8];
    const int l = blockIdx.x, tid = threadIdx.x;
    const float* yrow = y + (size_t)l * DINNER;
    const float* zrow = zx + (size_t)l * DPROJ;   // z = cols [0, DINNER)

    float part = 0.f;
    for (int i = tid; i < DINNER; i += 256) {
        const float z = zrow[i];
        const float g = z / (1.f + expf(-z));
        const float v = yrow[i] * g;
        buf[i] = v;
        part = fmaf(v, v, part);
    }
#pragma unroll
    for (int o = 16; o; o >>= 1) part += __shfl_xor_sync(0xffffffffu, part, o);
    if ((tid & 31) == 0) red[tid >> 5] = part;
    __syncthreads();
    if (tid < 8) {
        float v = red[tid];
#pragma unroll
        for (int o = 4; o; o >>= 1) v += __shfl_xor_sync(0xffu, v, o);
        if (tid == 0) red[0] = v;
    }
    __syncthreads();
    const float r = rsqrtf(red[0] / (float)DINNER + 1e-5f);
    for (int i = tid; i < DINNER; i += 256)
        yn[(size_t)l * DINNER + i] = buf[i] * r * nw[i];
}

// ---------------- launcher ---------------------------------------------------
extern "C" void kernel_launch(void* const* d_in, const int* in_sizes, int n_in,
                              void* d_out, int out_size)
{
    const float* u          = (const float*)d_in[0];
    const float* in_proj_w  = (const float*)d_in[1];
    const float* conv_w     = (const float*)d_in[2];
    const float* conv_b     = (const float*)d_in[3];
    const float* dt_bias    = (const float*)d_in[4];
    const float* A_log      = (const float*)d_in[5];
    const float* Dvec       = (const float*)d_in[6];
    const float* norm_w     = (const float*)d_in[7];
    const float* out_proj_w = (const float*)d_in[8];
    float* out = (float*)d_out;

    float *zx, *xBC, *dt, *dA, *y, *yn;
    cudaGetSymbolAddress((void**)&zx,  g_zxbcdt);
    cudaGetSymbolAddress((void**)&xBC, g_xBC);
    cudaGetSymbolAddress((void**)&dt,  g_dt);
    cudaGetSymbolAddress((void**)&dA,  g_dA);
    cudaGetSymbolAddress((void**)&y,   g_y);
    cudaGetSymbolAddress((void**)&yn,  g_yn);

    // 1) zxbcdt = u @ in_proj_w^T   (4096 x 8512, K=2048)
    mma_gemm_tn<<<dim3((DPROJ + 127) / 128, SEQLEN / 128), 256>>>(
        u, in_proj_w, zx, SEQLEN, DPROJ, DMODEL);

    // 2) causal depthwise conv + SiLU
    conv_silu_kernel<<<(SEQLEN * CONVDIM + 255) / 256, 256>>>(
        zx, conv_w, conv_b, xBC);

    // 3) dt / decay precompute
    dt_kernel<<<(SEQLEN * NHEADS + 255) / 256, 256>>>(
        zx, dt_bias, A_log, dt, dA);

    // 4) selective scan (+ D skip)
    scan_kernel<<<NHEADS * 4, 128>>>(xBC, dt, dA, Dvec, y);

    // 5) gate + RMSNorm
    gate_norm_kernel<<<SEQLEN, 256>>>(y, zx, norm_w, yn);

    // 6) out = yn @ out_proj_w^T   (4096 x 2048, K=4096)
    mma_gemm_tn<<<dim3(DMODEL / 128, SEQLEN / 128), 256>>>(
        yn, out_proj_w, out, SEQLEN, DMODEL, DINNER);
}